// round 1
// baseline (speedup 1.0000x reference)
#include <cuda_runtime.h>
#include <math.h>

// ---------------- problem constants ----------------
#define D_MODEL  1024
#define D_STATE  16
#define D_INNER  2048
#define DT_RANK  64
#define BATCH    2
#define LENGTH   2048
#define NROW     (BATCH * LENGTH)       // 4096
#define XDBL_N   96                     // dt_rank + 2*d_state

// ---------------- scratch (device globals; no allocation allowed) ----------------
__device__ float g_xz   [(size_t)NROW * (2 * D_INNER)];   // [row, 4096]  (x_inner | z)
__device__ float g_xconv[(size_t)NROW * D_INNER];         // [row, 2048]
__device__ float g_xdbl [(size_t)NROW * XDBL_N];          // [row, 96]  (dt_lowrank | B | C)
__device__ float g_dt   [(size_t)NROW * D_INNER];         // [row, 2048] softplus'd dt
__device__ float g_gate [(size_t)NROW * D_INNER];         // [row, 2048] (y)*silu(z)

// ---------------- generic tiled SGEMM: C[M,N] = A[M,K]@B[K,N] + bias, optional softplus ----
// BM=BN=128, BK=8, 256 threads, 8x8 per thread. M must be multiple of 128, K multiple of 8.
// N handled with guards (for N=96 case via other kernel; here N multiple of 4).
template <int SOFTPLUS>
__global__ __launch_bounds__(256) void sgemm128(
    const float* __restrict__ A, int lda,
    const float* __restrict__ B, int ldb,
    const float* __restrict__ bias,
    float* __restrict__ C, int ldc,
    int M, int N, int K)
{
    __shared__ float As[8][128];
    __shared__ float Bs[8][128];
    const int tid = threadIdx.x;
    const int m0 = blockIdx.y * 128;
    const int n0 = blockIdx.x * 128;
    const int tx = tid & 15, ty = tid >> 4;

    float acc[8][8];
#pragma unroll
    for (int i = 0; i < 8; i++)
#pragma unroll
        for (int j = 0; j < 8; j++) acc[i][j] = 0.f;

    const int ar = tid >> 1,  ak = (tid & 1) * 4;   // A tile: 128 rows x 8 k
    const int br = tid >> 5,  bc = (tid & 31) * 4;  // B tile: 8 rows x 128 cols

    // prefetch first tiles
    float4 av = *(const float4*)&A[(size_t)(m0 + ar) * lda + 0 + ak];
    float4 bv = make_float4(0.f, 0.f, 0.f, 0.f);
    if (n0 + bc < N)
        bv = *(const float4*)&B[(size_t)(0 + br) * ldb + n0 + bc];

    for (int k0 = 0; k0 < K; k0 += 8) {
        As[ak + 0][ar] = av.x; As[ak + 1][ar] = av.y;
        As[ak + 2][ar] = av.z; As[ak + 3][ar] = av.w;
        *(float4*)&Bs[br][bc] = bv;
        __syncthreads();

        if (k0 + 8 < K) {
            av = *(const float4*)&A[(size_t)(m0 + ar) * lda + (k0 + 8) + ak];
            bv = make_float4(0.f, 0.f, 0.f, 0.f);
            if (n0 + bc < N)
                bv = *(const float4*)&B[(size_t)(k0 + 8 + br) * ldb + n0 + bc];
        }

#pragma unroll
        for (int kk = 0; kk < 8; kk++) {
            float4 a0 = *(const float4*)&As[kk][ty * 8];
            float4 a1 = *(const float4*)&As[kk][ty * 8 + 4];
            float4 b0 = *(const float4*)&Bs[kk][tx * 8];
            float4 b1 = *(const float4*)&Bs[kk][tx * 8 + 4];
            float ra[8] = {a0.x, a0.y, a0.z, a0.w, a1.x, a1.y, a1.z, a1.w};
            float rb[8] = {b0.x, b0.y, b0.z, b0.w, b1.x, b1.y, b1.z, b1.w};
#pragma unroll
            for (int i = 0; i < 8; i++)
#pragma unroll
                for (int j = 0; j < 8; j++)
                    acc[i][j] = fmaf(ra[i], rb[j], acc[i][j]);
        }
        __syncthreads();
    }

#pragma unroll
    for (int i = 0; i < 8; i++) {
        const int row = m0 + ty * 8 + i;
#pragma unroll
        for (int j = 0; j < 8; j++) {
            const int col = n0 + tx * 8 + j;
            if (col < N) {
                float v = acc[i][j] + bias[col];
                if (SOFTPLUS) v = fmaxf(v, 0.f) + log1pf(expf(-fabsf(v)));
                C[(size_t)row * ldc + col] = v;
            }
        }
    }
}

// ---------------- skinny GEMM: x_dbl[M,96] = A[M,K] @ B[K,96] + bias ----------------
// TILE_M = 32 rows/block -> 128 blocks (keeps all SMs busy despite N=96).
__global__ __launch_bounds__(256) void gemm_n96(
    const float* __restrict__ A,   // [M,K]
    const float* __restrict__ B,   // [K,96]
    const float* __restrict__ bias,
    float* __restrict__ C,         // [M,96]
    int M, int K)
{
    __shared__ float As[32][33];
    __shared__ float Bs[32][96];
    const int tid = threadIdx.x;
    const int m0 = blockIdx.x * 32;
    const int r  = tid >> 3;          // 0..31 row within tile
    const int c0 = (tid & 7) * 12;    // 12 cols per thread

    float acc[12];
#pragma unroll
    for (int i = 0; i < 12; i++) acc[i] = 0.f;

    for (int k0 = 0; k0 < K; k0 += 32) {
        __syncthreads();
        {   // A: 32x32 floats, one float4 per thread
            int arow = tid >> 3, akk = (tid & 7) * 4;
            float4 v = *(const float4*)&A[(size_t)(m0 + arow) * K + k0 + akk];
            As[arow][akk + 0] = v.x; As[arow][akk + 1] = v.y;
            As[arow][akk + 2] = v.z; As[arow][akk + 3] = v.w;
        }
#pragma unroll
        for (int j = 0; j < 3; j++) {   // B: 32x96 floats = 768 float4
            int idx = tid + 256 * j;
            int brw = idx / 24, bcc = (idx % 24) * 4;
            float4 v = *(const float4*)&B[(size_t)(k0 + brw) * XDBL_N + bcc];
            *(float4*)&Bs[brw][bcc] = v;
        }
        __syncthreads();
#pragma unroll
        for (int kk = 0; kk < 32; kk++) {
            float a = As[r][kk];
#pragma unroll
            for (int i = 0; i < 12; i += 4) {
                float4 b4 = *(const float4*)&Bs[kk][c0 + i];
                acc[i + 0] = fmaf(a, b4.x, acc[i + 0]);
                acc[i + 1] = fmaf(a, b4.y, acc[i + 1]);
                acc[i + 2] = fmaf(a, b4.z, acc[i + 2]);
                acc[i + 3] = fmaf(a, b4.w, acc[i + 3]);
            }
        }
    }
#pragma unroll
    for (int i = 0; i < 12; i++)
        C[(size_t)(m0 + r) * XDBL_N + c0 + i] = acc[i] + bias[c0 + i];
}

// ---------------- depthwise causal mean-3 conv + SiLU ----------------
__global__ void conv_silu_kernel()
{
    const int i = blockIdx.x * blockDim.x + threadIdx.x;
    if (i >= NROW * D_INNER) return;
    const int d   = i & (D_INNER - 1);
    const int row = i >> 11;                 // b*L + t
    const int t   = row & (LENGTH - 1);
    const float* p = g_xz + (size_t)row * (2 * D_INNER) + d;
    float v = p[0];
    if (t >= 1) v += p[-(2 * D_INNER)];
    if (t >= 2) v += p[-2 * (2 * D_INNER)];
    v *= (1.0f / 3.0f);
    g_xconv[i] = v / (1.f + expf(-v));       // SiLU
}

// ---------------- selective scan + gating ----------------
// lane layout: n = lane&15 (state), half = lane>>4 -> 2 channels/warp,
// block = 256 threads = 16 channels of one batch. 32-step smem staging.
__global__ __launch_bounds__(256) void scan_kernel(const float* __restrict__ A_log,
                                                   const float* __restrict__ Dv)
{
    const int TT = 32;
    __shared__ float s_dt[TT][16], s_x[TT][16], s_B[TT][16], s_C[TT][16];

    const int tid  = threadIdx.x;
    const int b    = blockIdx.x >> 7;            // 128 blocks per batch
    const int d0   = (blockIdx.x & 127) << 4;
    const int lane = tid & 31, w = tid >> 5;
    const int half = lane >> 4, n = lane & 15;
    const int ch   = (w << 1) | half;            // channel within block (0..15)
    const int d    = d0 + ch;

    const float a  = -expf(A_log[d * D_STATE + n]);
    const float Dd = Dv[d];
    float h = 0.f;
    const size_t rowbase = (size_t)b * LENGTH;

    for (int t0 = 0; t0 < LENGTH; t0 += TT) {
        __syncthreads();
        for (int e = tid; e < TT * 16; e += 256) {
            const int tt = e >> 4, cc = e & 15;
            const size_t row = rowbase + t0 + tt;
            s_dt[tt][cc] = g_dt   [row * D_INNER + d0 + cc];
            s_x [tt][cc] = g_xconv[row * D_INNER + d0 + cc];
            s_B [tt][cc] = g_xdbl [row * XDBL_N + DT_RANK + cc];
            s_C [tt][cc] = g_xdbl [row * XDBL_N + DT_RANK + D_STATE + cc];
        }
        __syncthreads();
#pragma unroll 4
        for (int tt = 0; tt < TT; tt++) {
            const float dtv = s_dt[tt][ch];
            const float xv  = s_x [tt][ch];
            const float dA  = __expf(a * dtv);
            const float u   = dtv * xv;
            h = fmaf(dA, h, u * s_B[tt][n]);
            float yc = h * s_C[tt][n];
            yc += __shfl_xor_sync(0xffffffffu, yc, 8);
            yc += __shfl_xor_sync(0xffffffffu, yc, 4);
            yc += __shfl_xor_sync(0xffffffffu, yc, 2);
            yc += __shfl_xor_sync(0xffffffffu, yc, 1);
            if (n == 0) {
                const size_t row = rowbase + t0 + tt;
                const float zv = g_xz[row * (2 * D_INNER) + D_INNER + d];
                const float sz = zv / (1.f + __expf(-zv));
                const float y  = fmaf(xv, Dd, yc);
                g_gate[row * D_INNER + d] = y * sz;
            }
        }
    }
}

// ---------------- host launcher ----------------
extern "C" void kernel_launch(void* const* d_in, const int* in_sizes, int n_in,
                              void* d_out, int out_size)
{
    (void)in_sizes; (void)n_in; (void)out_size;
    const float* x     = (const float*)d_in[0];
    const float* W_in  = (const float*)d_in[1];
    const float* b_in  = (const float*)d_in[2];
    const float* W_x   = (const float*)d_in[3];
    const float* b_x   = (const float*)d_in[4];
    const float* W_dt  = (const float*)d_in[5];
    const float* b_dt  = (const float*)d_in[6];
    const float* A_log = (const float*)d_in[7];
    const float* Dp    = (const float*)d_in[8];
    const float* W_out = (const float*)d_in[9];
    const float* b_out = (const float*)d_in[10];
    float* out = (float*)d_out;

    float *xz, *xconv, *xdbl, *dt, *gate;
    cudaGetSymbolAddress((void**)&xz,    g_xz);
    cudaGetSymbolAddress((void**)&xconv, g_xconv);
    cudaGetSymbolAddress((void**)&xdbl,  g_xdbl);
    cudaGetSymbolAddress((void**)&dt,    g_dt);
    cudaGetSymbolAddress((void**)&gate,  g_gate);

    // 1) xz = x @ W_in + b_in            [4096,1024]@[1024,4096]
    sgemm128<0><<<dim3(4096 / 128, NROW / 128), 256>>>(
        x, D_MODEL, W_in, 2 * D_INNER, b_in, xz, 2 * D_INNER,
        NROW, 2 * D_INNER, D_MODEL);

    // 2) causal mean-3 conv + SiLU on x_inner half
    conv_silu_kernel<<<(NROW * D_INNER) / 256, 256>>>();

    // 3) x_dbl = x_conv @ W_x + b_x      [4096,2048]@[2048,96]
    gemm_n96<<<NROW / 32, 256>>>(xconv, W_x, b_x, xdbl, NROW, D_INNER);

    // 4) dt = softplus(x_dbl[:, :64] @ W_dt + b_dt)   [4096,64]@[64,2048]
    sgemm128<1><<<dim3(D_INNER / 128, NROW / 128), 256>>>(
        xdbl, XDBL_N, W_dt, D_INNER, b_dt, dt, D_INNER,
        NROW, D_INNER, DT_RANK);

    // 5) selective scan + skip(D) + gate by silu(z)
    scan_kernel<<<256, 256>>>(A_log, Dp);

    // 6) out = gate @ W_out + b_out      [4096,2048]@[2048,1024]
    sgemm128<0><<<dim3(D_MODEL / 128, NROW / 128), 256>>>(
        gate, D_INNER, W_out, D_MODEL, b_out, out, D_MODEL,
        NROW, D_MODEL, D_INNER);
}

// round 3
// speedup vs baseline: 1.2253x; 1.2253x over previous
#include <cuda_runtime.h>
#include <math.h>
#include <stdint.h>

// ---------------- problem constants ----------------
#define D_MODEL  1024
#define D_STATE  16
#define D_INNER  2048
#define DT_RANK  64
#define BATCH    2
#define LENGTH   2048
#define NROW     (BATCH * LENGTH)       // 4096
#define XDBL_N   96                     // dt_rank + 2*d_state

// ---------------- scratch (device globals; no allocation allowed) ----------------
__device__ __align__(256) float g_xz   [(size_t)NROW * (2 * D_INNER)];
__device__ __align__(256) float g_xconv[(size_t)NROW * D_INNER];
__device__ __align__(256) float g_xdbl [(size_t)NROW * XDBL_N];
__device__ __align__(256) float g_dt   [(size_t)NROW * D_INNER];
__device__ __align__(256) float g_gate [(size_t)NROW * D_INNER];
// transposed weights, [N,K] K-major
__device__ __align__(256) float g_WtIn [(size_t)(2 * D_INNER) * D_MODEL]; // [4096,1024]
__device__ __align__(256) float g_WtDt [(size_t)D_INNER * DT_RANK];       // [2048,64]
__device__ __align__(256) float g_WtOut[(size_t)D_MODEL * D_INNER];       // [1024,2048]

// ---------------- helpers ----------------
__device__ __forceinline__ uint32_t f2tf32(float x) {
    uint32_t r;
    asm("cvt.rna.tf32.f32 %0, %1;" : "=r"(r) : "f"(x));
    return r;
}
__device__ __forceinline__ void mma16n8k8(float c[4], const uint32_t a[4],
                                          const uint32_t b[2]) {
    asm volatile(
        "mma.sync.aligned.m16n8k8.row.col.f32.tf32.tf32.f32 "
        "{%0,%1,%2,%3}, {%4,%5,%6,%7}, {%8,%9}, {%0,%1,%2,%3};"
        : "+f"(c[0]), "+f"(c[1]), "+f"(c[2]), "+f"(c[3])
        : "r"(a[0]), "r"(a[1]), "r"(a[2]), "r"(a[3]), "r"(b[0]), "r"(b[1]));
}

// ---------------- tf32 mma.sync GEMM: C[M,N] = A[M,K] @ Bt[N,K]^T + bias ------------
// CTA tile 128x128, BK=16 double-buffered, 256 threads = 8 warps (2m x 4n),
// warp tile 64x32 = 4 m-atoms x 4 n-atoms of m16n8k8.
// SMEM layout word-offset: W(k, x) = k*128 + (x ^ ((k&3)<<3))  -> conflict-free
// for both staging STS and all fragment LDS.
template <int SOFTPLUS>
__global__ __launch_bounds__(256) void mma_gemm(
    const float* __restrict__ A,  int lda,
    const float* __restrict__ Bt, int ldb,
    const float* __restrict__ bias,
    float* __restrict__ C, int ldc, int K)
{
    __shared__ uint32_t As[2][16 * 128];
    __shared__ uint32_t Bs[2][16 * 128];

    const int tid  = threadIdx.x;
    const int lane = tid & 31;
    const int wid  = tid >> 5;
    const int wm   = wid >> 2;        // 0..1
    const int wn   = wid & 3;         // 0..3
    const int r    = lane >> 2;       // 0..7
    const int cq   = lane & 3;        // 0..3
    const int xorv = cq << 3;

    const int m0 = blockIdx.y * 128;
    const int n0 = blockIdx.x * 128;
    const float* Ag = A  + (size_t)m0 * lda;
    const float* Bg = Bt + (size_t)n0 * ldb;

    const int mm = tid & 127;         // staging row within tile
    const int kqb = tid >> 7;         // 0..1

    float acc[4][4][4];
#pragma unroll
    for (int i = 0; i < 4; i++)
#pragma unroll
        for (int j = 0; j < 4; j++)
#pragma unroll
            for (int q = 0; q < 4; q++) acc[i][j][q] = 0.f;

    const int NC = K >> 4;
    float4 pa[2], pb[2];

    // prefetch chunk 0
#pragma unroll
    for (int it = 0; it < 2; it++) {
        const int kq = kqb + it * 2;
        pa[it] = *(const float4*)(Ag + (size_t)mm * lda + kq * 4);
        pb[it] = *(const float4*)(Bg + (size_t)mm * ldb + kq * 4);
    }

    for (int c = 0; c < NC; c++) {
        const int buf = c & 1;
        // ---- store staged regs to smem (tf32-rounded, swizzled) ----
#pragma unroll
        for (int it = 0; it < 2; it++) {
            const int kq = kqb + it * 2;
            uint32_t* da = &As[buf][(kq * 4) * 128];
            uint32_t* db = &Bs[buf][(kq * 4) * 128];
            da[0 * 128 + (mm ^ 0)]  = f2tf32(pa[it].x);
            da[1 * 128 + (mm ^ 8)]  = f2tf32(pa[it].y);
            da[2 * 128 + (mm ^ 16)] = f2tf32(pa[it].z);
            da[3 * 128 + (mm ^ 24)] = f2tf32(pa[it].w);
            db[0 * 128 + (mm ^ 0)]  = f2tf32(pb[it].x);
            db[1 * 128 + (mm ^ 8)]  = f2tf32(pb[it].y);
            db[2 * 128 + (mm ^ 16)] = f2tf32(pb[it].z);
            db[3 * 128 + (mm ^ 24)] = f2tf32(pb[it].w);
        }
        __syncthreads();

        // ---- prefetch next chunk (overlaps mma below) ----
        if (c + 1 < NC) {
            const int k0 = (c + 1) << 4;
#pragma unroll
            for (int it = 0; it < 2; it++) {
                const int kq = kqb + it * 2;
                pa[it] = *(const float4*)(Ag + (size_t)mm * lda + k0 + kq * 4);
                pb[it] = *(const float4*)(Bg + (size_t)mm * ldb + k0 + kq * 4);
            }
        }

        // ---- compute: 2 k-steps of 8 ----
        const uint32_t* A_s = As[buf];
        const uint32_t* B_s = Bs[buf];
#pragma unroll
        for (int ks = 0; ks < 2; ks++) {
            const int kbase = (ks * 8 + cq) * 128;
            uint32_t a[4][4], b[4][2];
#pragma unroll
            for (int mi = 0; mi < 4; mi++) {
                const int rb = wm * 64 + mi * 16 + r;
                const int o0 = kbase + (rb ^ xorv);
                const int o1 = kbase + ((rb + 8) ^ xorv);
                a[mi][0] = A_s[o0];        a[mi][1] = A_s[o1];
                a[mi][2] = A_s[o0 + 512];  a[mi][3] = A_s[o1 + 512];
            }
#pragma unroll
            for (int ni = 0; ni < 4; ni++) {
                const int nb = wn * 32 + ni * 8 + r;
                const int o  = kbase + (nb ^ xorv);
                b[ni][0] = B_s[o];  b[ni][1] = B_s[o + 512];
            }
#pragma unroll
            for (int mi = 0; mi < 4; mi++)
#pragma unroll
                for (int ni = 0; ni < 4; ni++)
                    mma16n8k8(acc[mi][ni], a[mi], b[ni]);
        }
        __syncthreads();
    }

    // ---- epilogue: bias (+optional softplus), direct global stores ----
#pragma unroll
    for (int ni = 0; ni < 4; ni++) {
        const int col = n0 + wn * 32 + ni * 8 + cq * 2;
        const float bv0 = bias[col], bv1 = bias[col + 1];
#pragma unroll
        for (int mi = 0; mi < 4; mi++) {
            const int row0 = m0 + wm * 64 + mi * 16 + r;
            float2 o0, o1;
            o0.x = acc[mi][ni][0] + bv0;  o0.y = acc[mi][ni][1] + bv1;
            o1.x = acc[mi][ni][2] + bv0;  o1.y = acc[mi][ni][3] + bv1;
            if (SOFTPLUS) {
                o0.x = fmaxf(o0.x, 0.f) + log1pf(expf(-fabsf(o0.x)));
                o0.y = fmaxf(o0.y, 0.f) + log1pf(expf(-fabsf(o0.y)));
                o1.x = fmaxf(o1.x, 0.f) + log1pf(expf(-fabsf(o1.x)));
                o1.y = fmaxf(o1.y, 0.f) + log1pf(expf(-fabsf(o1.y)));
            }
            *(float2*)(C + (size_t)row0 * ldc + col)       = o0;
            *(float2*)(C + (size_t)(row0 + 8) * ldc + col) = o1;
        }
    }
}

// ---------------- weight transpose: D[C][R] = S[R][C] ----------------
__global__ __launch_bounds__(256) void transpose_kernel(
    const float* __restrict__ S, float* __restrict__ D, int R, int C)
{
    __shared__ float t[32][33];
    const int c0 = blockIdx.x * 32, r0 = blockIdx.y * 32;
    const int x = threadIdx.x, y = threadIdx.y;   // 32 x 8
#pragma unroll
    for (int i = 0; i < 32; i += 8)
        t[y + i][x] = S[(size_t)(r0 + y + i) * C + c0 + x];
    __syncthreads();
#pragma unroll
    for (int i = 0; i < 32; i += 8)
        D[(size_t)(c0 + y + i) * R + r0 + x] = t[x][y + i];
}

// ---------------- skinny GEMM: x_dbl[M,96] = A[M,K] @ B[K,96] + bias ----------------
__global__ __launch_bounds__(256) void gemm_n96(
    const float* __restrict__ A,
    const float* __restrict__ B,
    const float* __restrict__ bias,
    float* __restrict__ C,
    int M, int K)
{
    __shared__ float As[32][33];
    __shared__ float Bs[32][96];
    const int tid = threadIdx.x;
    const int m0 = blockIdx.x * 32;
    const int r  = tid >> 3;
    const int c0 = (tid & 7) * 12;

    float acc[12];
#pragma unroll
    for (int i = 0; i < 12; i++) acc[i] = 0.f;

    for (int k0 = 0; k0 < K; k0 += 32) {
        __syncthreads();
        {
            int arow = tid >> 3, akk = (tid & 7) * 4;
            float4 v = *(const float4*)&A[(size_t)(m0 + arow) * K + k0 + akk];
            As[arow][akk + 0] = v.x; As[arow][akk + 1] = v.y;
            As[arow][akk + 2] = v.z; As[arow][akk + 3] = v.w;
        }
#pragma unroll
        for (int j = 0; j < 3; j++) {
            int idx = tid + 256 * j;
            int brw = idx / 24, bcc = (idx % 24) * 4;
            float4 v = *(const float4*)&B[(size_t)(k0 + brw) * XDBL_N + bcc];
            *(float4*)&Bs[brw][bcc] = v;
        }
        __syncthreads();
#pragma unroll
        for (int kk = 0; kk < 32; kk++) {
            float a = As[r][kk];
#pragma unroll
            for (int i = 0; i < 12; i += 4) {
                float4 b4 = *(const float4*)&Bs[kk][c0 + i];
                acc[i + 0] = fmaf(a, b4.x, acc[i + 0]);
                acc[i + 1] = fmaf(a, b4.y, acc[i + 1]);
                acc[i + 2] = fmaf(a, b4.z, acc[i + 2]);
                acc[i + 3] = fmaf(a, b4.w, acc[i + 3]);
            }
        }
    }
#pragma unroll
    for (int i = 0; i < 12; i++)
        C[(size_t)(m0 + r) * XDBL_N + c0 + i] = acc[i] + bias[c0 + i];
}

// ---------------- depthwise causal mean-3 conv + SiLU ----------------
__global__ void conv_silu_kernel()
{
    const int i = blockIdx.x * blockDim.x + threadIdx.x;
    if (i >= NROW * D_INNER) return;
    const int d   = i & (D_INNER - 1);
    const int row = i >> 11;
    const int t   = row & (LENGTH - 1);
    const float* p = g_xz + (size_t)row * (2 * D_INNER) + d;
    float v = p[0];
    if (t >= 1) v += p[-(2 * D_INNER)];
    if (t >= 2) v += p[-2 * (2 * D_INNER)];
    v *= (1.0f / 3.0f);
    g_xconv[i] = v / (1.f + expf(-v));
}

// ---------------- selective scan + gating ----------------
__global__ __launch_bounds__(256) void scan_kernel(const float* __restrict__ A_log,
                                                   const float* __restrict__ Dv)
{
    const int TT = 32;
    __shared__ float s_dt[TT][16], s_x[TT][16], s_B[TT][16], s_C[TT][16];

    const int tid  = threadIdx.x;
    const int b    = blockIdx.x >> 7;
    const int d0   = (blockIdx.x & 127) << 4;
    const int lane = tid & 31, w = tid >> 5;
    const int half = lane >> 4, n = lane & 15;
    const int ch   = (w << 1) | half;
    const int d    = d0 + ch;

    const float a  = -expf(A_log[d * D_STATE + n]);
    const float Dd = Dv[d];
    float h = 0.f;
    const size_t rowbase = (size_t)b * LENGTH;

    for (int t0 = 0; t0 < LENGTH; t0 += TT) {
        __syncthreads();
        for (int e = tid; e < TT * 16; e += 256) {
            const int tt = e >> 4, cc = e & 15;
            const size_t row = rowbase + t0 + tt;
            s_dt[tt][cc] = g_dt   [row * D_INNER + d0 + cc];
            s_x [tt][cc] = g_xconv[row * D_INNER + d0 + cc];
            s_B [tt][cc] = g_xdbl [row * XDBL_N + DT_RANK + cc];
            s_C [tt][cc] = g_xdbl [row * XDBL_N + DT_RANK + D_STATE + cc];
        }
        __syncthreads();
#pragma unroll 4
        for (int tt = 0; tt < TT; tt++) {
            const float dtv = s_dt[tt][ch];
            const float xv  = s_x [tt][ch];
            const float dA  = __expf(a * dtv);
            const float u   = dtv * xv;
            h = fmaf(dA, h, u * s_B[tt][n]);
            float yc = h * s_C[tt][n];
            yc += __shfl_xor_sync(0xffffffffu, yc, 8);
            yc += __shfl_xor_sync(0xffffffffu, yc, 4);
            yc += __shfl_xor_sync(0xffffffffu, yc, 2);
            yc += __shfl_xor_sync(0xffffffffu, yc, 1);
            if (n == 0) {
                const size_t row = rowbase + t0 + tt;
                const float zv = g_xz[row * (2 * D_INNER) + D_INNER + d];
                const float sz = zv / (1.f + __expf(-zv));
                const float y  = fmaf(xv, Dd, yc);
                g_gate[row * D_INNER + d] = y * sz;
            }
        }
    }
}

// ---------------- host launcher ----------------
extern "C" void kernel_launch(void* const* d_in, const int* in_sizes, int n_in,
                              void* d_out, int out_size)
{
    (void)in_sizes; (void)n_in; (void)out_size;
    const float* x     = (const float*)d_in[0];
    const float* W_in  = (const float*)d_in[1];
    const float* b_in  = (const float*)d_in[2];
    const float* W_x   = (const float*)d_in[3];
    const float* b_x   = (const float*)d_in[4];
    const float* W_dt  = (const float*)d_in[5];
    const float* b_dt  = (const float*)d_in[6];
    const float* A_log = (const float*)d_in[7];
    const float* Dp    = (const float*)d_in[8];
    const float* W_out = (const float*)d_in[9];
    const float* b_out = (const float*)d_in[10];
    float* out = (float*)d_out;

    float *xz, *xconv, *xdbl, *dt, *gate, *WtIn, *WtDt, *WtOut;
    cudaGetSymbolAddress((void**)&xz,    g_xz);
    cudaGetSymbolAddress((void**)&xconv, g_xconv);
    cudaGetSymbolAddress((void**)&xdbl,  g_xdbl);
    cudaGetSymbolAddress((void**)&dt,    g_dt);
    cudaGetSymbolAddress((void**)&gate,  g_gate);
    cudaGetSymbolAddress((void**)&WtIn,  g_WtIn);
    cudaGetSymbolAddress((void**)&WtDt,  g_WtDt);
    cudaGetSymbolAddress((void**)&WtOut, g_WtOut);

    // 0) transpose weights to [N,K]
    transpose_kernel<<<dim3(4096 / 32, 1024 / 32), dim3(32, 8)>>>(W_in,  WtIn,  1024, 4096);
    transpose_kernel<<<dim3(2048 / 32,   64 / 32), dim3(32, 8)>>>(W_dt,  WtDt,    64, 2048);
    transpose_kernel<<<dim3(1024 / 32, 2048 / 32), dim3(32, 8)>>>(W_out, WtOut, 2048, 1024);

    // 1) xz = x @ W_in + b_in      [4096,1024] x [1024,4096]
    mma_gemm<0><<<dim3(4096 / 128, NROW / 128), 256>>>(
        x, D_MODEL, WtIn, D_MODEL, b_in, xz, 2 * D_INNER, D_MODEL);

    // 2) causal mean-3 conv + SiLU
    conv_silu_kernel<<<(NROW * D_INNER) / 256, 256>>>();

    // 3) x_dbl = x_conv @ W_x + b_x   [4096,2048] x [2048,96]
    gemm_n96<<<NROW / 32, 256>>>(xconv, W_x, b_x, xdbl, NROW, D_INNER);

    // 4) dt = softplus(x_dbl[:, :64] @ W_dt + b_dt)  [4096,64] x [64,2048]
    mma_gemm<1><<<dim3(D_INNER / 128, NROW / 128), 256>>>(
        xdbl, XDBL_N, WtDt, DT_RANK, b_dt, dt, D_INNER, DT_RANK);

    // 5) selective scan + skip(D) + gate by silu(z)
    scan_kernel<<<256, 256>>>(A_log, Dp);

    // 6) out = gate @ W_out + b_out   [4096,2048] x [2048,1024]
    mma_gemm<0><<<dim3(D_MODEL / 128, NROW / 128), 256>>>(
        gate, D_INNER, WtOut, D_INNER, b_out, out, D_MODEL, D_INNER);
}

// round 4
// speedup vs baseline: 1.4206x; 1.1594x over previous
#include <cuda_runtime.h>
#include <math.h>
#include <stdint.h>

// ---------------- problem constants ----------------
#define D_MODEL  1024
#define D_STATE  16
#define D_INNER  2048
#define DT_RANK  64
#define BATCH    2
#define LENGTH   2048
#define NROW     (BATCH * LENGTH)       // 4096
#define XDBL_N   96                     // dt_rank + 2*d_state

// ---------------- scratch (device globals; no allocation allowed) ----------------
__device__ __align__(256) float g_xz   [(size_t)NROW * (2 * D_INNER)];
__device__ __align__(256) float g_xconv[(size_t)NROW * D_INNER];
__device__ __align__(256) float g_xdbl [(size_t)NROW * XDBL_N];
__device__ __align__(256) float g_dt   [(size_t)NROW * D_INNER];
__device__ __align__(256) float g_gate [(size_t)NROW * D_INNER];   // tf32-rounded
__device__ __align__(256) float g_xr   [(size_t)NROW * D_MODEL];   // tf32-rounded x
// transposed weights, [N,K] K-major, tf32-rounded
__device__ __align__(256) float g_WtIn [(size_t)(2 * D_INNER) * D_MODEL];
__device__ __align__(256) float g_WtDt [(size_t)D_INNER * DT_RANK];
__device__ __align__(256) float g_WtOut[(size_t)D_MODEL * D_INNER];

// ---------------- helpers ----------------
__device__ __forceinline__ uint32_t f2tf32(float x) {
    uint32_t r;
    asm("cvt.rna.tf32.f32 %0, %1;" : "=r"(r) : "f"(x));
    return r;
}
__device__ __forceinline__ float roundtf(float x) {
    return __uint_as_float(f2tf32(x));
}
__device__ __forceinline__ uint32_t smem_u32(const void* p) {
    uint32_t a;
    asm("{ .reg .u64 t; cvta.to.shared.u64 t, %1; cvt.u32.u64 %0, t; }"
        : "=r"(a) : "l"(p));
    return a;
}
__device__ __forceinline__ void cp16(uint32_t dst, const float* src) {
    asm volatile("cp.async.cg.shared.global [%0], [%1], 16;"
                 :: "r"(dst), "l"(src) : "memory");
}
#define CP_COMMIT() asm volatile("cp.async.commit_group;" ::: "memory")
#define CP_WAIT2()  asm volatile("cp.async.wait_group 2;"  ::: "memory")

__device__ __forceinline__ void mma16n8k8(float c[4], const uint32_t a[4],
                                          const uint32_t b[2]) {
    asm volatile(
        "mma.sync.aligned.m16n8k8.row.col.f32.tf32.tf32.f32 "
        "{%0,%1,%2,%3}, {%4,%5,%6,%7}, {%8,%9}, {%0,%1,%2,%3};"
        : "+f"(c[0]), "+f"(c[1]), "+f"(c[2]), "+f"(c[3])
        : "r"(a[0]), "r"(a[1]), "r"(a[2]), "r"(a[3]), "r"(b[0]), "r"(b[1]));
}

// ---------------- tf32 mma.sync GEMM, cp.async 4-stage pipeline ----------------
// C[M,N] = A[M,K] @ Bt[N,K]^T + bias.  Inputs MUST be pre-rounded to tf32.
// CTA tile 128x128, BK=16, 256 threads = 8 warps (2m x 4n), warp tile 64x32.
// SMEM per stage: [row 0..127][k 0..15], quad-swizzled:
//   word(row,k) = row*16 + ((k>>2) ^ ((row>>1)&3))*4 + (k&3)
// -> conflict-free for 16B cp.async writes and all fragment LDS.
template <int SOFTPLUS>
__global__ __launch_bounds__(256) void mma_gemm(
    const float* __restrict__ A,  int lda,
    const float* __restrict__ Bt, int ldb,
    const float* __restrict__ bias,
    float* __restrict__ C, int ldc, int K)
{
    extern __shared__ uint32_t sm[];     // As[4][2048] | Bs[4][2048]
    uint32_t* As = sm;
    uint32_t* Bs = sm + 4 * 2048;
    const uint32_t sA = smem_u32(As);
    const uint32_t sB = smem_u32(Bs);

    const int tid  = threadIdx.x;
    const int lane = tid & 31;
    const int wid  = tid >> 5;
    const int wm   = wid >> 2;        // 0..1
    const int wn   = wid & 3;         // 0..3
    const int r    = lane >> 2;       // 0..7
    const int cq   = lane & 3;        // 0..3

    const int m0 = blockIdx.y * 128;
    const int n0 = blockIdx.x * 128;
    const float* Ag = A  + (size_t)m0 * lda;
    const float* Bg = Bt + (size_t)n0 * ldb;

    // staging map: each thread issues 2 A + 2 B cp.asyncs per stage
    const int srow = tid & 127;
    const int sq0  = tid >> 7;                 // quads {sq0, sq0+2}
    const uint32_t ssw = (srow >> 1) & 3;

    float acc[4][4][4];
#pragma unroll
    for (int i = 0; i < 4; i++)
#pragma unroll
        for (int j = 0; j < 4; j++)
#pragma unroll
            for (int q = 0; q < 4; q++) acc[i][j][q] = 0.f;

    const int NC = K >> 4;

    // ---- issue one stage's loads ----
    auto issue = [&](int stage, int chunk) {
        const int k0 = chunk << 4;
#pragma unroll
        for (int t = 0; t < 2; t++) {
            const int q = sq0 + t * 2;
            const uint32_t woff = (uint32_t)(stage * 2048 + srow * 16 +
                                             (((uint32_t)q ^ ssw) << 2)) << 2;
            cp16(sA + woff, Ag + (size_t)srow * lda + k0 + q * 4);
            cp16(sB + woff, Bg + (size_t)srow * ldb + k0 + q * 4);
        }
    };

    // prologue: 3 stages in flight (always commit 3 groups)
#pragma unroll
    for (int s = 0; s < 3; s++) {
        if (s < NC) issue(s, s);
        CP_COMMIT();
    }

    for (int c = 0; c < NC; c++) {
        CP_WAIT2();
        __syncthreads();

        const uint32_t* A_s = As + (c & 3) * 2048;
        const uint32_t* B_s = Bs + (c & 3) * 2048;
#pragma unroll
        for (int ks = 0; ks < 2; ks++) {
            uint32_t a[4][4], b[4][2];
#pragma unroll
            for (int mi = 0; mi < 4; mi++) {
                const int rb  = wm * 64 + mi * 16 + r;
                const uint32_t swa = (rb >> 1) & 3;
                const int q0 = (2 * ks) ^ swa, q1 = (2 * ks + 1) ^ swa;
                const int b0 = rb * 16 + cq, b8 = (rb + 8) * 16 + cq;
                a[mi][0] = A_s[b0 + (q0 << 2)];
                a[mi][1] = A_s[b8 + (q0 << 2)];
                a[mi][2] = A_s[b0 + (q1 << 2)];
                a[mi][3] = A_s[b8 + (q1 << 2)];
            }
#pragma unroll
            for (int ni = 0; ni < 4; ni++) {
                const int nb = wn * 32 + ni * 8 + r;
                const uint32_t swb = (nb >> 1) & 3;
                const int base = nb * 16 + cq;
                b[ni][0] = B_s[base + ((((2 * ks)     ^ swb)) << 2)];
                b[ni][1] = B_s[base + ((((2 * ks + 1) ^ swb)) << 2)];
            }
#pragma unroll
            for (int mi = 0; mi < 4; mi++)
#pragma unroll
                for (int ni = 0; ni < 4; ni++)
                    mma16n8k8(acc[mi][ni], a[mi], b[ni]);
        }

        if (c + 3 < NC) issue((c + 3) & 3, c + 3);
        CP_COMMIT();
    }

    // ---- epilogue ----
#pragma unroll
    for (int ni = 0; ni < 4; ni++) {
        const int col = n0 + wn * 32 + ni * 8 + cq * 2;
        const float bv0 = bias[col], bv1 = bias[col + 1];
#pragma unroll
        for (int mi = 0; mi < 4; mi++) {
            const int row0 = m0 + wm * 64 + mi * 16 + r;
            float2 o0, o1;
            o0.x = acc[mi][ni][0] + bv0;  o0.y = acc[mi][ni][1] + bv1;
            o1.x = acc[mi][ni][2] + bv0;  o1.y = acc[mi][ni][3] + bv1;
            if (SOFTPLUS) {
                o0.x = fmaxf(o0.x, 0.f) + log1pf(expf(-fabsf(o0.x)));
                o0.y = fmaxf(o0.y, 0.f) + log1pf(expf(-fabsf(o0.y)));
                o1.x = fmaxf(o1.x, 0.f) + log1pf(expf(-fabsf(o1.x)));
                o1.y = fmaxf(o1.y, 0.f) + log1pf(expf(-fabsf(o1.y)));
            }
            *(float2*)(C + (size_t)row0 * ldc + col)       = o0;
            *(float2*)(C + (size_t)(row0 + 8) * ldc + col) = o1;
        }
    }
}

// ---------------- weight transpose (+ tf32 round): D[C][R] = rnd(S[R][C]) ----------
__global__ __launch_bounds__(256) void transpose_round_kernel(
    const float* __restrict__ S, float* __restrict__ D, int R, int C)
{
    __shared__ float t[32][33];
    const int c0 = blockIdx.x * 32, r0 = blockIdx.y * 32;
    const int x = threadIdx.x, y = threadIdx.y;   // 32 x 8
#pragma unroll
    for (int i = 0; i < 32; i += 8)
        t[y + i][x] = S[(size_t)(r0 + y + i) * C + c0 + x];
    __syncthreads();
#pragma unroll
    for (int i = 0; i < 32; i += 8)
        D[(size_t)(c0 + y + i) * R + r0 + x] = roundtf(t[x][y + i]);
}

// ---------------- elementwise tf32 round (float4) ----------------
__global__ void round_tf32_kernel(const float* __restrict__ S,
                                  float* __restrict__ D, int n4)
{
    const int i = blockIdx.x * blockDim.x + threadIdx.x;
    if (i >= n4) return;
    float4 v = ((const float4*)S)[i];
    v.x = roundtf(v.x); v.y = roundtf(v.y);
    v.z = roundtf(v.z); v.w = roundtf(v.w);
    ((float4*)D)[i] = v;
}

// ---------------- skinny GEMM: x_dbl[M,96] = A[M,K] @ B[K,96] + bias ----------------
// cols < DT_RANK are tf32-rounded on store (they feed the dt MMA only).
__global__ __launch_bounds__(256) void gemm_n96(
    const float* __restrict__ A,
    const float* __restrict__ B,
    const float* __restrict__ bias,
    float* __restrict__ C,
    int M, int K)
{
    __shared__ float As[32][33];
    __shared__ float Bs[32][96];
    const int tid = threadIdx.x;
    const int m0 = blockIdx.x * 32;
    const int r  = tid >> 3;
    const int c0 = (tid & 7) * 12;

    float acc[12];
#pragma unroll
    for (int i = 0; i < 12; i++) acc[i] = 0.f;

    for (int k0 = 0; k0 < K; k0 += 32) {
        __syncthreads();
        {
            int arow = tid >> 3, akk = (tid & 7) * 4;
            float4 v = *(const float4*)&A[(size_t)(m0 + arow) * K + k0 + akk];
            As[arow][akk + 0] = v.x; As[arow][akk + 1] = v.y;
            As[arow][akk + 2] = v.z; As[arow][akk + 3] = v.w;
        }
#pragma unroll
        for (int j = 0; j < 3; j++) {
            int idx = tid + 256 * j;
            int brw = idx / 24, bcc = (idx % 24) * 4;
            float4 v = *(const float4*)&B[(size_t)(k0 + brw) * XDBL_N + bcc];
            *(float4*)&Bs[brw][bcc] = v;
        }
        __syncthreads();
#pragma unroll
        for (int kk = 0; kk < 32; kk++) {
            float a = As[r][kk];
#pragma unroll
            for (int i = 0; i < 12; i += 4) {
                float4 b4 = *(const float4*)&Bs[kk][c0 + i];
                acc[i + 0] = fmaf(a, b4.x, acc[i + 0]);
                acc[i + 1] = fmaf(a, b4.y, acc[i + 1]);
                acc[i + 2] = fmaf(a, b4.z, acc[i + 2]);
                acc[i + 3] = fmaf(a, b4.w, acc[i + 3]);
            }
        }
    }
#pragma unroll
    for (int i = 0; i < 12; i++) {
        float v = acc[i] + bias[c0 + i];
        if (c0 + i < DT_RANK) v = roundtf(v);
        C[(size_t)(m0 + r) * XDBL_N + c0 + i] = v;
    }
}

// ---------------- depthwise causal mean-3 conv + SiLU ----------------
__global__ void conv_silu_kernel()
{
    const int i = blockIdx.x * blockDim.x + threadIdx.x;
    if (i >= NROW * D_INNER) return;
    const int d   = i & (D_INNER - 1);
    const int row = i >> 11;
    const int t   = row & (LENGTH - 1);
    const float* p = g_xz + (size_t)row * (2 * D_INNER) + d;
    float v = p[0];
    if (t >= 1) v += p[-(2 * D_INNER)];
    if (t >= 2) v += p[-2 * (2 * D_INNER)];
    v *= (1.0f / 3.0f);
    g_xconv[i] = v / (1.f + expf(-v));
}

// ---------------- selective scan + gating (gate stored tf32-rounded) ----------------
__global__ __launch_bounds__(256) void scan_kernel(const float* __restrict__ A_log,
                                                   const float* __restrict__ Dv)
{
    const int TT = 32;
    __shared__ float s_dt[TT][16], s_x[TT][16], s_B[TT][16], s_C[TT][16];

    const int tid  = threadIdx.x;
    const int b    = blockIdx.x >> 7;
    const int d0   = (blockIdx.x & 127) << 4;
    const int lane = tid & 31, w = tid >> 5;
    const int half = lane >> 4, n = lane & 15;
    const int ch   = (w << 1) | half;
    const int d    = d0 + ch;

    const float a  = -expf(A_log[d * D_STATE + n]);
    const float Dd = Dv[d];
    float h = 0.f;
    const size_t rowbase = (size_t)b * LENGTH;

    for (int t0 = 0; t0 < LENGTH; t0 += TT) {
        __syncthreads();
        for (int e = tid; e < TT * 16; e += 256) {
            const int tt = e >> 4, cc = e & 15;
            const size_t row = rowbase + t0 + tt;
            s_dt[tt][cc] = g_dt   [row * D_INNER + d0 + cc];
            s_x [tt][cc] = g_xconv[row * D_INNER + d0 + cc];
            s_B [tt][cc] = g_xdbl [row * XDBL_N + DT_RANK + cc];
            s_C [tt][cc] = g_xdbl [row * XDBL_N + DT_RANK + D_STATE + cc];
        }
        __syncthreads();
#pragma unroll 4
        for (int tt = 0; tt < TT; tt++) {
            const float dtv = s_dt[tt][ch];
            const float xv  = s_x [tt][ch];
            const float dA  = __expf(a * dtv);
            const float u   = dtv * xv;
            h = fmaf(dA, h, u * s_B[tt][n]);
            float yc = h * s_C[tt][n];
            yc += __shfl_xor_sync(0xffffffffu, yc, 8);
            yc += __shfl_xor_sync(0xffffffffu, yc, 4);
            yc += __shfl_xor_sync(0xffffffffu, yc, 2);
            yc += __shfl_xor_sync(0xffffffffu, yc, 1);
            if (n == 0) {
                const size_t row = rowbase + t0 + tt;
                const float zv = g_xz[row * (2 * D_INNER) + D_INNER + d];
                const float sz = zv / (1.f + __expf(-zv));
                const float y  = fmaf(xv, Dd, yc);
                g_gate[row * D_INNER + d] = roundtf(y * sz);
            }
        }
    }
}

// ---------------- host launcher ----------------
extern "C" void kernel_launch(void* const* d_in, const int* in_sizes, int n_in,
                              void* d_out, int out_size)
{
    (void)in_sizes; (void)n_in; (void)out_size;
    const float* x     = (const float*)d_in[0];
    const float* W_in  = (const float*)d_in[1];
    const float* b_in  = (const float*)d_in[2];
    const float* W_x   = (const float*)d_in[3];
    const float* b_x   = (const float*)d_in[4];
    const float* W_dt  = (const float*)d_in[5];
    const float* b_dt  = (const float*)d_in[6];
    const float* A_log = (const float*)d_in[7];
    const float* Dp    = (const float*)d_in[8];
    const float* W_out = (const float*)d_in[9];
    const float* b_out = (const float*)d_in[10];
    float* out = (float*)d_out;

    float *xz, *xconv, *xdbl, *dt, *gate, *xr, *WtIn, *WtDt, *WtOut;
    cudaGetSymbolAddress((void**)&xz,    g_xz);
    cudaGetSymbolAddress((void**)&xconv, g_xconv);
    cudaGetSymbolAddress((void**)&xdbl,  g_xdbl);
    cudaGetSymbolAddress((void**)&dt,    g_dt);
    cudaGetSymbolAddress((void**)&gate,  g_gate);
    cudaGetSymbolAddress((void**)&xr,    g_xr);
    cudaGetSymbolAddress((void**)&WtIn,  g_WtIn);
    cudaGetSymbolAddress((void**)&WtDt,  g_WtDt);
    cudaGetSymbolAddress((void**)&WtOut, g_WtOut);

    const int DSMEM = 65536;   // 4 stages x (8KB A + 8KB B)
    cudaFuncSetAttribute(mma_gemm<0>, cudaFuncAttributeMaxDynamicSharedMemorySize, DSMEM);
    cudaFuncSetAttribute(mma_gemm<1>, cudaFuncAttributeMaxDynamicSharedMemorySize, DSMEM);

    // 0) pre-round inputs + transpose weights to [N,K] (tf32-rounded)
    round_tf32_kernel<<<(NROW * D_MODEL / 4 + 255) / 256, 256>>>(x, xr, NROW * D_MODEL / 4);
    transpose_round_kernel<<<dim3(4096 / 32, 1024 / 32), dim3(32, 8)>>>(W_in,  WtIn,  1024, 4096);
    transpose_round_kernel<<<dim3(2048 / 32,   64 / 32), dim3(32, 8)>>>(W_dt,  WtDt,    64, 2048);
    transpose_round_kernel<<<dim3(1024 / 32, 2048 / 32), dim3(32, 8)>>>(W_out, WtOut, 2048, 1024);

    // 1) xz = x @ W_in + b_in      [4096,1024] x [1024,4096]
    mma_gemm<0><<<dim3(4096 / 128, NROW / 128), 256, DSMEM>>>(
        xr, D_MODEL, WtIn, D_MODEL, b_in, xz, 2 * D_INNER, D_MODEL);

    // 2) causal mean-3 conv + SiLU
    conv_silu_kernel<<<(NROW * D_INNER) / 256, 256>>>();

    // 3) x_dbl = x_conv @ W_x + b_x   [4096,2048] x [2048,96]
    gemm_n96<<<NROW / 32, 256>>>(xconv, W_x, b_x, xdbl, NROW, D_INNER);

    // 4) dt = softplus(x_dbl[:, :64] @ W_dt + b_dt)  [4096,64] x [64,2048]
    mma_gemm<1><<<dim3(D_INNER / 128, NROW / 128), 256, DSMEM>>>(
        xdbl, XDBL_N, WtDt, DT_RANK, b_dt, dt, D_INNER, DT_RANK);

    // 5) selective scan + skip(D) + gate by silu(z)
    scan_kernel<<<256, 256>>>(A_log, Dp);

    // 6) out = gate @ W_out + b_out   [4096,2048] x [2048,1024]
    mma_gemm<0><<<dim3(D_MODEL / 128, NROW / 128), 256, DSMEM>>>(
        gate, D_INNER, WtOut, D_INNER, b_out, out, D_MODEL, D_INNER);
}

// round 5
// speedup vs baseline: 2.3569x; 1.6591x over previous
#include <cuda_runtime.h>
#include <math.h>
#include <stdint.h>

// ---------------- problem constants ----------------
#define D_MODEL  1024
#define D_STATE  16
#define D_INNER  2048
#define DT_RANK  64
#define BATCH    2
#define LENGTH   2048
#define NROW     (BATCH * LENGTH)       // 4096
#define XDBL_N   96                     // dt_rank + 2*d_state
#define NCH      16                     // scan time-chunks
#define CL       (LENGTH / NCH)         // 128 steps per chunk
#define NDN      (BATCH * D_INNER * D_STATE)   // 65536 (b,d,n) tuples

// ---------------- scratch (device globals; no allocation allowed) ----------------
__device__ __align__(256) float g_xz   [(size_t)NROW * (2 * D_INNER)];
__device__ __align__(256) float g_xconv[(size_t)NROW * D_INNER];
__device__ __align__(256) float g_xdbl [(size_t)NROW * XDBL_N];
__device__ __align__(256) float g_dt   [(size_t)NROW * D_INNER];
__device__ __align__(256) float g_gate [(size_t)NROW * D_INNER];   // tf32-rounded
__device__ __align__(256) float g_xr   [(size_t)NROW * D_MODEL];   // tf32-rounded x
// transposed weights, [N,K] K-major, tf32-rounded
__device__ __align__(256) float g_WtIn [(size_t)(2 * D_INNER) * D_MODEL];
__device__ __align__(256) float g_WtDt [(size_t)D_INNER * DT_RANK];
__device__ __align__(256) float g_WtOut[(size_t)D_MODEL * D_INNER];
// scan chunk transitions: layout [chunk][(b*D_INNER+d)*D_STATE+n]
__device__ __align__(256) float g_P [(size_t)NCH * NDN];
__device__ __align__(256) float g_S [(size_t)NCH * NDN];
__device__ __align__(256) float g_h0[(size_t)NCH * NDN];

// ---------------- helpers ----------------
__device__ __forceinline__ uint32_t f2tf32(float x) {
    uint32_t r;
    asm("cvt.rna.tf32.f32 %0, %1;" : "=r"(r) : "f"(x));
    return r;
}
__device__ __forceinline__ float roundtf(float x) {
    return __uint_as_float(f2tf32(x));
}
__device__ __forceinline__ uint32_t smem_u32(const void* p) {
    uint32_t a;
    asm("{ .reg .u64 t; cvta.to.shared.u64 t, %1; cvt.u32.u64 %0, t; }"
        : "=r"(a) : "l"(p));
    return a;
}
__device__ __forceinline__ void cp16(uint32_t dst, const float* src) {
    asm volatile("cp.async.cg.shared.global [%0], [%1], 16;"
                 :: "r"(dst), "l"(src) : "memory");
}
#define CP_COMMIT() asm volatile("cp.async.commit_group;" ::: "memory")
#define CP_WAIT2()  asm volatile("cp.async.wait_group 2;"  ::: "memory")

__device__ __forceinline__ void mma16n8k8(float c[4], const uint32_t a[4],
                                          const uint32_t b[2]) {
    asm volatile(
        "mma.sync.aligned.m16n8k8.row.col.f32.tf32.tf32.f32 "
        "{%0,%1,%2,%3}, {%4,%5,%6,%7}, {%8,%9}, {%0,%1,%2,%3};"
        : "+f"(c[0]), "+f"(c[1]), "+f"(c[2]), "+f"(c[3])
        : "r"(a[0]), "r"(a[1]), "r"(a[2]), "r"(a[3]), "r"(b[0]), "r"(b[1]));
}

// ---------------- tf32 mma.sync GEMM, cp.async 4-stage pipeline, 2 CTAs/SM --------
// C[M,N] = A[M,K] @ Bt[N,K]^T + bias.  Inputs MUST be pre-rounded to tf32.
// CTA tile 128x128, BK=16, 256 threads = 8 warps (2m x 4n), warp tile 64x32.
// SMEM word(row,k) = row*16 + ((k>>2) ^ ((row>>1)&3))*4 + (k&3) -> conflict-free.
template <int SOFTPLUS>
__global__ __launch_bounds__(256, 2) void mma_gemm(
    const float* __restrict__ A,  int lda,
    const float* __restrict__ Bt, int ldb,
    const float* __restrict__ bias,
    float* __restrict__ C, int ldc, int K)
{
    extern __shared__ uint32_t sm[];     // As[4][2048] | Bs[4][2048]
    uint32_t* As = sm;
    uint32_t* Bs = sm + 4 * 2048;
    const uint32_t sA = smem_u32(As);
    const uint32_t sB = smem_u32(Bs);

    const int tid  = threadIdx.x;
    const int lane = tid & 31;
    const int wid  = tid >> 5;
    const int wm   = wid >> 2;        // 0..1
    const int wn   = wid & 3;         // 0..3
    const int r    = lane >> 2;       // 0..7
    const int cq   = lane & 3;        // 0..3

    const int m0 = blockIdx.y * 128;
    const int n0 = blockIdx.x * 128;
    const float* Ag = A  + (size_t)m0 * lda;
    const float* Bg = Bt + (size_t)n0 * ldb;

    const int srow = tid & 127;
    const int sq0  = tid >> 7;                 // quads {sq0, sq0+2}
    const uint32_t ssw = (srow >> 1) & 3;

    float acc[4][4][4];
#pragma unroll
    for (int i = 0; i < 4; i++)
#pragma unroll
        for (int j = 0; j < 4; j++)
#pragma unroll
            for (int q = 0; q < 4; q++) acc[i][j][q] = 0.f;

    const int NC = K >> 4;

    auto issue = [&](int stage, int chunk) {
        const int k0 = chunk << 4;
#pragma unroll
        for (int t = 0; t < 2; t++) {
            const int q = sq0 + t * 2;
            const uint32_t woff = (uint32_t)(stage * 2048 + srow * 16 +
                                             (((uint32_t)q ^ ssw) << 2)) << 2;
            cp16(sA + woff, Ag + (size_t)srow * lda + k0 + q * 4);
            cp16(sB + woff, Bg + (size_t)srow * ldb + k0 + q * 4);
        }
    };

#pragma unroll
    for (int s = 0; s < 3; s++) {
        if (s < NC) issue(s, s);
        CP_COMMIT();
    }

    for (int c = 0; c < NC; c++) {
        CP_WAIT2();
        __syncthreads();

        const uint32_t* A_s = As + (c & 3) * 2048;
        const uint32_t* B_s = Bs + (c & 3) * 2048;
#pragma unroll
        for (int ks = 0; ks < 2; ks++) {
            uint32_t a[4][4], b[4][2];
#pragma unroll
            for (int mi = 0; mi < 4; mi++) {
                const int rb  = wm * 64 + mi * 16 + r;
                const uint32_t swa = (rb >> 1) & 3;
                const int q0 = (2 * ks) ^ swa, q1 = (2 * ks + 1) ^ swa;
                const int b0 = rb * 16 + cq, b8 = (rb + 8) * 16 + cq;
                a[mi][0] = A_s[b0 + (q0 << 2)];
                a[mi][1] = A_s[b8 + (q0 << 2)];
                a[mi][2] = A_s[b0 + (q1 << 2)];
                a[mi][3] = A_s[b8 + (q1 << 2)];
            }
#pragma unroll
            for (int ni = 0; ni < 4; ni++) {
                const int nb = wn * 32 + ni * 8 + r;
                const uint32_t swb = (nb >> 1) & 3;
                const int base = nb * 16 + cq;
                b[ni][0] = B_s[base + ((((2 * ks)     ^ swb)) << 2)];
                b[ni][1] = B_s[base + ((((2 * ks + 1) ^ swb)) << 2)];
            }
#pragma unroll
            for (int mi = 0; mi < 4; mi++)
#pragma unroll
                for (int ni = 0; ni < 4; ni++)
                    mma16n8k8(acc[mi][ni], a[mi], b[ni]);
        }

        if (c + 3 < NC) issue((c + 3) & 3, c + 3);
        CP_COMMIT();
    }

#pragma unroll
    for (int ni = 0; ni < 4; ni++) {
        const int col = n0 + wn * 32 + ni * 8 + cq * 2;
        const float bv0 = bias[col], bv1 = bias[col + 1];
#pragma unroll
        for (int mi = 0; mi < 4; mi++) {
            const int row0 = m0 + wm * 64 + mi * 16 + r;
            float2 o0, o1;
            o0.x = acc[mi][ni][0] + bv0;  o0.y = acc[mi][ni][1] + bv1;
            o1.x = acc[mi][ni][2] + bv0;  o1.y = acc[mi][ni][3] + bv1;
            if (SOFTPLUS) {
                o0.x = fmaxf(o0.x, 0.f) + log1pf(expf(-fabsf(o0.x)));
                o0.y = fmaxf(o0.y, 0.f) + log1pf(expf(-fabsf(o0.y)));
                o1.x = fmaxf(o1.x, 0.f) + log1pf(expf(-fabsf(o1.x)));
                o1.y = fmaxf(o1.y, 0.f) + log1pf(expf(-fabsf(o1.y)));
            }
            *(float2*)(C + (size_t)row0 * ldc + col)       = o0;
            *(float2*)(C + (size_t)(row0 + 8) * ldc + col) = o1;
        }
    }
}

// ---------------- weight transpose (+ tf32 round): D[C][R] = rnd(S[R][C]) ----------
__global__ __launch_bounds__(256) void transpose_round_kernel(
    const float* __restrict__ S, float* __restrict__ D, int R, int C)
{
    __shared__ float t[32][33];
    const int c0 = blockIdx.x * 32, r0 = blockIdx.y * 32;
    const int x = threadIdx.x, y = threadIdx.y;   // 32 x 8
#pragma unroll
    for (int i = 0; i < 32; i += 8)
        t[y + i][x] = S[(size_t)(r0 + y + i) * C + c0 + x];
    __syncthreads();
#pragma unroll
    for (int i = 0; i < 32; i += 8)
        D[(size_t)(c0 + y + i) * R + r0 + x] = roundtf(t[x][y + i]);
}

// ---------------- elementwise tf32 round (float4) ----------------
__global__ void round_tf32_kernel(const float* __restrict__ S,
                                  float* __restrict__ D, int n4)
{
    const int i = blockIdx.x * blockDim.x + threadIdx.x;
    if (i >= n4) return;
    float4 v = ((const float4*)S)[i];
    v.x = roundtf(v.x); v.y = roundtf(v.y);
    v.z = roundtf(v.z); v.w = roundtf(v.w);
    ((float4*)D)[i] = v;
}

// ---------------- skinny GEMM: x_dbl[M,96] = A[M,K] @ B[K,96] + bias ----------------
__global__ __launch_bounds__(256) void gemm_n96(
    const float* __restrict__ A,
    const float* __restrict__ B,
    const float* __restrict__ bias,
    float* __restrict__ C,
    int M, int K)
{
    __shared__ float As[32][33];
    __shared__ float Bs[32][96];
    const int tid = threadIdx.x;
    const int m0 = blockIdx.x * 32;
    const int r  = tid >> 3;
    const int c0 = (tid & 7) * 12;

    float acc[12];
#pragma unroll
    for (int i = 0; i < 12; i++) acc[i] = 0.f;

    for (int k0 = 0; k0 < K; k0 += 32) {
        __syncthreads();
        {
            int arow = tid >> 3, akk = (tid & 7) * 4;
            float4 v = *(const float4*)&A[(size_t)(m0 + arow) * K + k0 + akk];
            As[arow][akk + 0] = v.x; As[arow][akk + 1] = v.y;
            As[arow][akk + 2] = v.z; As[arow][akk + 3] = v.w;
        }
#pragma unroll
        for (int j = 0; j < 3; j++) {
            int idx = tid + 256 * j;
            int brw = idx / 24, bcc = (idx % 24) * 4;
            float4 v = *(const float4*)&B[(size_t)(k0 + brw) * XDBL_N + bcc];
            *(float4*)&Bs[brw][bcc] = v;
        }
        __syncthreads();
#pragma unroll
        for (int kk = 0; kk < 32; kk++) {
            float a = As[r][kk];
#pragma unroll
            for (int i = 0; i < 12; i += 4) {
                float4 b4 = *(const float4*)&Bs[kk][c0 + i];
                acc[i + 0] = fmaf(a, b4.x, acc[i + 0]);
                acc[i + 1] = fmaf(a, b4.y, acc[i + 1]);
                acc[i + 2] = fmaf(a, b4.z, acc[i + 2]);
                acc[i + 3] = fmaf(a, b4.w, acc[i + 3]);
            }
        }
    }
#pragma unroll
    for (int i = 0; i < 12; i++) {
        float v = acc[i] + bias[c0 + i];
        if (c0 + i < DT_RANK) v = roundtf(v);
        C[(size_t)(m0 + r) * XDBL_N + c0 + i] = v;
    }
}

// ---------------- depthwise causal mean-3 conv + SiLU ----------------
__global__ void conv_silu_kernel()
{
    const int i = blockIdx.x * blockDim.x + threadIdx.x;
    if (i >= NROW * D_INNER) return;
    const int d   = i & (D_INNER - 1);
    const int row = i >> 11;
    const int t   = row & (LENGTH - 1);
    const float* p = g_xz + (size_t)row * (2 * D_INNER) + d;
    float v = p[0];
    if (t >= 1) v += p[-(2 * D_INNER)];
    if (t >= 2) v += p[-2 * (2 * D_INNER)];
    v *= (1.0f / 3.0f);
    g_xconv[i] = v / (1.f + __expf(-v));
}

// ======================= 3-phase chunked selective scan =======================
// block mapping (phases 1,3): blockIdx.x = ((b*128 + dblk)*NCH + chunk)
// 256 threads: warp w, half=lane>>4, n=lane&15; channel ch = (w<<1)|half.

// ---- phase 1: per-chunk transition (P = prod dA, S = h starting from 0) ----
__global__ __launch_bounds__(256) void scan_p1(const float* __restrict__ A_log)
{
    const int TT = 32;
    __shared__ float s_dt[TT][16], s_x[TT][16], s_B[TT][16];

    const int tid   = threadIdx.x;
    const int chunk = blockIdx.x & (NCH - 1);
    const int dblk  = (blockIdx.x >> 4) & 127;
    const int b     = blockIdx.x >> 11;
    const int d0    = dblk << 4;
    const int lane  = tid & 31, w = tid >> 5;
    const int half  = lane >> 4, n = lane & 15;
    const int ch    = (w << 1) | half;
    const int d     = d0 + ch;

    const float a = -__expf(A_log[d * D_STATE + n]);
    float h = 0.f, P = 1.f;
    const size_t rowbase = (size_t)b * LENGTH + (size_t)chunk * CL;

    for (int t0 = 0; t0 < CL; t0 += TT) {
        __syncthreads();
        for (int e = tid; e < TT * 16; e += 256) {
            const int tt = e >> 4, cc = e & 15;
            const size_t row = rowbase + t0 + tt;
            s_dt[tt][cc] = g_dt   [row * D_INNER + d0 + cc];
            s_x [tt][cc] = g_xconv[row * D_INNER + d0 + cc];
            s_B [tt][cc] = g_xdbl [row * XDBL_N + DT_RANK + cc];
        }
        __syncthreads();
#pragma unroll 8
        for (int tt = 0; tt < TT; tt++) {
            const float dtv = s_dt[tt][ch];
            const float dA  = __expf(a * dtv);
            P *= dA;
            h = fmaf(dA, h, dtv * s_x[tt][ch] * s_B[tt][n]);
        }
    }
    const size_t idx = ((size_t)b * D_INNER + d) * D_STATE + n;
    g_P[(size_t)chunk * NDN + idx] = P;
    g_S[(size_t)chunk * NDN + idx] = h;
}

// ---- phase 2: serial combine across chunks, emit per-chunk initial state ----
__global__ __launch_bounds__(256) void scan_p2()
{
    const int i = blockIdx.x * blockDim.x + threadIdx.x;   // 0..NDN-1
    if (i >= NDN) return;
    float h = 0.f;
#pragma unroll
    for (int c = 0; c < NCH; c++) {
        g_h0[(size_t)c * NDN + i] = h;
        h = fmaf(g_P[(size_t)c * NDN + i], h, g_S[(size_t)c * NDN + i]);
    }
}

// ---- phase 3: full scan per chunk from h0, emit gated output ----
__global__ __launch_bounds__(256) void scan_p3(const float* __restrict__ A_log,
                                               const float* __restrict__ Dv)
{
    const int TT = 32;
    __shared__ float s_dt[TT][16], s_x[TT][16], s_B[TT][16], s_C[TT][16];

    const int tid   = threadIdx.x;
    const int chunk = blockIdx.x & (NCH - 1);
    const int dblk  = (blockIdx.x >> 4) & 127;
    const int b     = blockIdx.x >> 11;
    const int d0    = dblk << 4;
    const int lane  = tid & 31, w = tid >> 5;
    const int half  = lane >> 4, n = lane & 15;
    const int ch    = (w << 1) | half;
    const int d     = d0 + ch;

    const float a  = -__expf(A_log[d * D_STATE + n]);
    const float Dd = Dv[d];
    const size_t idx = ((size_t)b * D_INNER + d) * D_STATE + n;
    float h = g_h0[(size_t)chunk * NDN + idx];
    const size_t rowbase = (size_t)b * LENGTH + (size_t)chunk * CL;

    for (int t0 = 0; t0 < CL; t0 += TT) {
        __syncthreads();
        for (int e = tid; e < TT * 16; e += 256) {
            const int tt = e >> 4, cc = e & 15;
            const size_t row = rowbase + t0 + tt;
            s_dt[tt][cc] = g_dt   [row * D_INNER + d0 + cc];
            s_x [tt][cc] = g_xconv[row * D_INNER + d0 + cc];
            s_B [tt][cc] = g_xdbl [row * XDBL_N + DT_RANK + cc];
            s_C [tt][cc] = g_xdbl [row * XDBL_N + DT_RANK + D_STATE + cc];
        }
        __syncthreads();
#pragma unroll 4
        for (int tt = 0; tt < TT; tt++) {
            const float dtv = s_dt[tt][ch];
            const float xv  = s_x [tt][ch];
            const float dA  = __expf(a * dtv);
            h = fmaf(dA, h, dtv * xv * s_B[tt][n]);
            float yc = h * s_C[tt][n];
            yc += __shfl_xor_sync(0xffffffffu, yc, 8);
            yc += __shfl_xor_sync(0xffffffffu, yc, 4);
            yc += __shfl_xor_sync(0xffffffffu, yc, 2);
            yc += __shfl_xor_sync(0xffffffffu, yc, 1);
            if (n == 0) {
                const size_t row = rowbase + t0 + tt;
                const float zv = g_xz[row * (2 * D_INNER) + D_INNER + d];
                const float sz = zv / (1.f + __expf(-zv));
                const float y  = fmaf(xv, Dd, yc);
                g_gate[row * D_INNER + d] = roundtf(y * sz);
            }
        }
    }
}

// ---------------- host launcher ----------------
extern "C" void kernel_launch(void* const* d_in, const int* in_sizes, int n_in,
                              void* d_out, int out_size)
{
    (void)in_sizes; (void)n_in; (void)out_size;
    const float* x     = (const float*)d_in[0];
    const float* W_in  = (const float*)d_in[1];
    const float* b_in  = (const float*)d_in[2];
    const float* W_x   = (const float*)d_in[3];
    const float* b_x   = (const float*)d_in[4];
    const float* W_dt  = (const float*)d_in[5];
    const float* b_dt  = (const float*)d_in[6];
    const float* A_log = (const float*)d_in[7];
    const float* Dp    = (const float*)d_in[8];
    const float* W_out = (const float*)d_in[9];
    const float* b_out = (const float*)d_in[10];
    float* out = (float*)d_out;

    float *xz, *xconv, *xdbl, *dt, *gate, *xr, *WtIn, *WtDt, *WtOut;
    cudaGetSymbolAddress((void**)&xz,    g_xz);
    cudaGetSymbolAddress((void**)&xconv, g_xconv);
    cudaGetSymbolAddress((void**)&xdbl,  g_xdbl);
    cudaGetSymbolAddress((void**)&dt,    g_dt);
    cudaGetSymbolAddress((void**)&gate,  g_gate);
    cudaGetSymbolAddress((void**)&xr,    g_xr);
    cudaGetSymbolAddress((void**)&WtIn,  g_WtIn);
    cudaGetSymbolAddress((void**)&WtDt,  g_WtDt);
    cudaGetSymbolAddress((void**)&WtOut, g_WtOut);

    const int DSMEM = 65536;   // 4 stages x (8KB A + 8KB B)
    cudaFuncSetAttribute(mma_gemm<0>, cudaFuncAttributeMaxDynamicSharedMemorySize, DSMEM);
    cudaFuncSetAttribute(mma_gemm<1>, cudaFuncAttributeMaxDynamicSharedMemorySize, DSMEM);

    // 0-2) pre-round x, transpose W_in / W_dt
    round_tf32_kernel<<<(NROW * D_MODEL / 4 + 255) / 256, 256>>>(x, xr, NROW * D_MODEL / 4);
    transpose_round_kernel<<<dim3(4096 / 32, 1024 / 32), dim3(32, 8)>>>(W_in, WtIn, 1024, 4096);
    transpose_round_kernel<<<dim3(2048 / 32,   64 / 32), dim3(32, 8)>>>(W_dt, WtDt,   64, 2048);

    // 3) xz = x @ W_in + b_in      [4096,1024] x [1024,4096]   <- profiled slot
    mma_gemm<0><<<dim3(4096 / 128, NROW / 128), 256, DSMEM>>>(
        xr, D_MODEL, WtIn, D_MODEL, b_in, xz, 2 * D_INNER, D_MODEL);

    // 4) causal mean-3 conv + SiLU
    conv_silu_kernel<<<(NROW * D_INNER) / 256, 256>>>();

    // 5) x_dbl = x_conv @ W_x + b_x   [4096,2048] x [2048,96]
    gemm_n96<<<NROW / 32, 256>>>(xconv, W_x, b_x, xdbl, NROW, D_INNER);

    // 6) dt = softplus(x_dbl[:, :64] @ W_dt + b_dt)  [4096,64] x [64,2048]
    mma_gemm<1><<<dim3(D_INNER / 128, NROW / 128), 256, DSMEM>>>(
        xdbl, XDBL_N, WtDt, DT_RANK, b_dt, dt, D_INNER, DT_RANK);

    // 7-9) chunked selective scan
    scan_p1<<<BATCH * 128 * NCH, 256>>>(A_log);
    scan_p2<<<NDN / 256, 256>>>();
    scan_p3<<<BATCH * 128 * NCH, 256>>>(A_log, Dp);

    // 10) transpose W_out (independent; placed late on purpose)
    transpose_round_kernel<<<dim3(1024 / 32, 2048 / 32), dim3(32, 8)>>>(W_out, WtOut, 2048, 1024);

    // 11) out = gate @ W_out + b_out   [4096,2048] x [2048,1024]
    mma_gemm<0><<<dim3(D_MODEL / 128, NROW / 128), 256, DSMEM>>>(
        gate, D_INNER, WtOut, D_INNER, b_out, out, D_MODEL, D_INNER);
}